// round 2
// baseline (speedup 1.0000x reference)
#include <cuda_runtime.h>

// Upsample_72619307041391
// x: (32, 512, 512, 1) f32, kernel: (4,4) f32 -> out: (32, 1024, 1024, 1) f32
//
// out = conv1d_horiz( repeat2x2(x), kernel.flatten()[1x16], SAME(pad_left=7) )
// Collapsed: output rows duplicated in pairs; even output cols are a 9-tap FIR
// on x (offsets -4..+4, weights se), odd cols an 8-tap FIR (offsets -3..+4, so).
//
// Thread t of a row covers x-cols 4t..4t+3 -> output cols 8t..8t+7 (x2 rows).
// Footprint x[4t-4..4t+7] = 3 aligned float4 loads. No shared memory.

#define W_IN    512
#define W_OUT   1024
#define TPR     128          // threads per x-row (512/4)

__global__ __launch_bounds__(256)
void upfir_kernel(const float* __restrict__ x,
                  const float* __restrict__ ker,
                  float* __restrict__ out)
{
    const int t    = threadIdx.x & (TPR - 1);     // 0..127 within row
    const int half = threadIdx.x >> 7;            // 0/1: which row of the pair
    const int row  = blockIdx.x * 2 + half;       // n*512 + r

    // Combined phase weights from the 16-tap FIR (uniform broadcast loads).
    float k[16];
    #pragma unroll
    for (int i = 0; i < 16; i++) k[i] = __ldg(ker + i);
    float se[9], so[8];
    se[0] = k[0];
    #pragma unroll
    for (int d = 1; d < 8; d++) se[d] = k[2*d - 1] + k[2*d];
    se[8] = k[15];
    #pragma unroll
    for (int d = 0; d < 8; d++) so[d] = k[2*d] + k[2*d + 1];

    // Load 12-value footprint: xs[j] = x[row, 4t + j - 4], zero outside [0,512)
    const float4* xr4 = reinterpret_cast<const float4*>(x + (size_t)row * W_IN);
    const float4 zero4 = make_float4(0.f, 0.f, 0.f, 0.f);
    float4 a = (t > 0)          ? __ldg(xr4 + (t - 1)) : zero4;
    float4 b =                    __ldg(xr4 + t);
    float4 c = (t < TPR - 1)    ? __ldg(xr4 + (t + 1)) : zero4;

    float xs[12] = { a.x, a.y, a.z, a.w,
                     b.x, b.y, b.z, b.w,
                     c.x, c.y, c.z, c.w };

    // e_i = out col 8t+2i, o_i = out col 8t+2i+1   (i = 0..3)
    float e0=0.f, e1=0.f, e2=0.f, e3=0.f;
    float o0=0.f, o1=0.f, o2=0.f, o3=0.f;
    #pragma unroll
    for (int d = 0; d < 9; d++) {
        const float w = se[d];
        e0 = fmaf(w, xs[d    ], e0);
        e1 = fmaf(w, xs[d + 1], e1);
        e2 = fmaf(w, xs[d + 2], e2);
        e3 = fmaf(w, xs[d + 3], e3);
    }
    #pragma unroll
    for (int d = 0; d < 8; d++) {
        const float w = so[d];
        o0 = fmaf(w, xs[d + 1], o0);
        o1 = fmaf(w, xs[d + 2], o1);
        o2 = fmaf(w, xs[d + 3], o2);
        o3 = fmaf(w, xs[d + 4], o3);
    }

    const float4 v0 = make_float4(e0, o0, e1, o1);
    const float4 v1 = make_float4(e2, o2, e3, o3);

    const int n = row >> 9;
    const int r = row & 511;
    float* o = out + (((size_t)n * 1024 + 2 * (size_t)r) * W_OUT) + 8 * (size_t)t;

    // duplicated rows 2r and 2r+1; streaming stores (output never re-read)
    __stcs(reinterpret_cast<float4*>(o),              v0);
    __stcs(reinterpret_cast<float4*>(o) + 1,          v1);
    __stcs(reinterpret_cast<float4*>(o + W_OUT),      v0);
    __stcs(reinterpret_cast<float4*>(o + W_OUT) + 1,  v1);
}

extern "C" void kernel_launch(void* const* d_in, const int* in_sizes, int n_in,
                              void* d_out, int out_size)
{
    const float* x   = (const float*)d_in[0];   // 32*512*512
    const float* ker = (const float*)d_in[1];   // 16 floats (4x4 row-major)
    float* out = (float*)d_out;                 // 32*1024*1024

    dim3 grid(32 * 512 / 2);   // 8192 blocks, 2 x-rows each
    dim3 block(256);
    upfir_kernel<<<grid, block>>>(x, ker, out);
}

// round 3
// speedup vs baseline: 1.1478x; 1.1478x over previous
#include <cuda_runtime.h>
#include <cstdint>

// Upsample_72619307041391
// x: (32, 512, 512, 1) f32, kernel: (4,4) f32 -> out: (32, 1024, 1024, 1) f32
//
// out = conv1d_horiz( repeat2x2(x), kernel.flatten()[1x16], SAME(pad_left=7) )
// Collapsed: output row pairs (2r, 2r+1) are identical; even output cols are a
// 9-tap FIR on x (offsets -4..+4), odd cols an 8-tap FIR (offsets -3..+4).
//
// R3: stores go via TMA bulk (SMEM -> GMEM). Output rows 2r and 2r+1 are
// contiguous (8KB), so each computed row is duplicated in SMEM and written
// with a single 8KB cp.async.bulk. No STG in the kernel at all.

#define W_IN    512
#define W_OUT   1024
#define TPR     128          // threads per x-row (512/4)

__device__ __forceinline__ uint32_t smem_u32(const void* p) {
    uint32_t a;
    asm("{ .reg .u64 t; cvta.to.shared.u64 t, %1; cvt.u32.u64 %0, t; }"
        : "=r"(a) : "l"(p));
    return a;
}

__global__ __launch_bounds__(256)
void upfir_kernel(const float* __restrict__ x,
                  const float* __restrict__ ker,
                  float* __restrict__ out)
{
    // srow[half] holds one output row duplicated twice: [0..1023] and [1024..2047]
    __shared__ __align__(16) float srow[2][2 * W_OUT];

    const int t    = threadIdx.x & (TPR - 1);     // 0..127 within row
    const int half = threadIdx.x >> 7;            // 0/1: which input row of pair
    const int row  = blockIdx.x * 2 + half;       // n*512 + r

    // Combined phase weights from the 16-tap FIR (uniform broadcast loads).
    float k[16];
    #pragma unroll
    for (int i = 0; i < 16; i++) k[i] = __ldg(ker + i);
    float se[9], so[8];
    se[0] = k[0];
    #pragma unroll
    for (int d = 1; d < 8; d++) se[d] = k[2*d - 1] + k[2*d];
    se[8] = k[15];
    #pragma unroll
    for (int d = 0; d < 8; d++) so[d] = k[2*d] + k[2*d + 1];

    // Load 12-value footprint: xs[j] = x[row, 4t + j - 4], zero outside [0,512)
    const float4* xr4 = reinterpret_cast<const float4*>(x + (size_t)row * W_IN);
    const float4 zero4 = make_float4(0.f, 0.f, 0.f, 0.f);
    float4 a = (t > 0)       ? __ldg(xr4 + (t - 1)) : zero4;
    float4 b =                 __ldg(xr4 + t);
    float4 c = (t < TPR - 1) ? __ldg(xr4 + (t + 1)) : zero4;

    float xs[12] = { a.x, a.y, a.z, a.w,
                     b.x, b.y, b.z, b.w,
                     c.x, c.y, c.z, c.w };

    float e0=0.f, e1=0.f, e2=0.f, e3=0.f;
    float o0=0.f, o1=0.f, o2=0.f, o3=0.f;
    #pragma unroll
    for (int d = 0; d < 9; d++) {
        const float w = se[d];
        e0 = fmaf(w, xs[d    ], e0);
        e1 = fmaf(w, xs[d + 1], e1);
        e2 = fmaf(w, xs[d + 2], e2);
        e3 = fmaf(w, xs[d + 3], e3);
    }
    #pragma unroll
    for (int d = 0; d < 8; d++) {
        const float w = so[d];
        o0 = fmaf(w, xs[d + 1], o0);
        o1 = fmaf(w, xs[d + 2], o1);
        o2 = fmaf(w, xs[d + 3], o2);
        o3 = fmaf(w, xs[d + 4], o3);
    }

    const float4 v0 = make_float4(e0, o0, e1, o1);
    const float4 v1 = make_float4(e2, o2, e3, o3);

    // Duplicate the row inside SMEM: copies at +0 and +1024 floats.
    float4* s = reinterpret_cast<float4*>(&srow[half][8 * t]);
    s[0]   = v0;
    s[1]   = v1;
    float4* s2 = reinterpret_cast<float4*>(&srow[half][W_OUT + 8 * t]);
    s2[0]  = v0;
    s2[1]  = v1;

    __syncthreads();
    // Order generic-proxy SMEM writes before async-proxy (TMA) reads.
    asm volatile("fence.proxy.async.shared::cta;" ::: "memory");

    if (threadIdx.x < 2) {
        const int rrow = blockIdx.x * 2 + threadIdx.x;        // this half's row
        const int n = rrow >> 9;
        const int r = rrow & 511;
        float* dst = out + ((size_t)n * 1024 + 2 * (size_t)r) * W_OUT;
        uint32_t src = smem_u32(&srow[threadIdx.x][0]);
        asm volatile(
            "cp.async.bulk.global.shared::cta.bulk_group [%0], [%1], %2;"
            :: "l"(dst), "r"(src), "r"(2 * W_OUT * 4) : "memory");
        asm volatile("cp.async.bulk.commit_group;" ::: "memory");
        // Full completion before CTA exit (SMEM lifetime + visibility).
        asm volatile("cp.async.bulk.wait_group 0;" ::: "memory");
    }
}

extern "C" void kernel_launch(void* const* d_in, const int* in_sizes, int n_in,
                              void* d_out, int out_size)
{
    const float* x   = (const float*)d_in[0];   // 32*512*512
    const float* ker = (const float*)d_in[1];   // 16 floats (4x4 row-major)
    float* out = (float*)d_out;                 // 32*1024*1024

    dim3 grid(32 * 512 / 2);   // 8192 blocks, 2 input rows each
    dim3 block(256);
    upfir_kernel<<<grid, block>>>(x, ker, out);
}

// round 4
// speedup vs baseline: 1.1514x; 1.0031x over previous
#include <cuda_runtime.h>
#include <cstdint>

// Upsample_72619307041391
// x: (32, 512, 512, 1) f32, kernel: (4,4) f32 -> out: (32, 1024, 1024, 1) f32
//
// out = conv1d_horiz( repeat2x2(x), kernel.flatten()[1x16], SAME(pad_left=7) )
// Collapsed: output row pairs (2r, 2r+1) are identical; even output cols are a
// 9-tap FIR on x (offsets -4..+4), odd cols an 8-tap FIR (offsets -3..+4).
//
// R4: one SMEM copy per computed row (4KB); duplication done by issuing TWO
// 4KB TMA bulk stores from the same SMEM. Kernel weights loaded as 4x LDG.128.

#define W_IN    512
#define W_OUT   1024
#define TPR     128          // threads per x-row (512/4)

__device__ __forceinline__ uint32_t smem_u32(const void* p) {
    uint32_t a;
    asm("{ .reg .u64 t; cvta.to.shared.u64 t, %1; cvt.u32.u64 %0, t; }"
        : "=r"(a) : "l"(p));
    return a;
}

__global__ __launch_bounds__(256)
void upfir_kernel(const float* __restrict__ x,
                  const float* __restrict__ ker,
                  float* __restrict__ out)
{
    // One 1024-float output row per half (no duplication in SMEM).
    __shared__ __align__(16) float srow[2][W_OUT];

    const int t    = threadIdx.x & (TPR - 1);     // 0..127 within row
    const int half = threadIdx.x >> 7;            // 0/1: which input row of pair
    const int row  = blockIdx.x * 2 + half;       // n*512 + r

    // FIR taps: 16 contiguous floats -> 4 vector loads (uniform broadcast).
    const float4* k4 = reinterpret_cast<const float4*>(ker);
    const float4 ka = __ldg(k4 + 0);
    const float4 kb = __ldg(k4 + 1);
    const float4 kc = __ldg(k4 + 2);
    const float4 kd = __ldg(k4 + 3);
    const float k[16] = { ka.x, ka.y, ka.z, ka.w,
                          kb.x, kb.y, kb.z, kb.w,
                          kc.x, kc.y, kc.z, kc.w,
                          kd.x, kd.y, kd.z, kd.w };

    // Combined phase weights.
    float se[9], so[8];
    se[0] = k[0];
    #pragma unroll
    for (int d = 1; d < 8; d++) se[d] = k[2*d - 1] + k[2*d];
    se[8] = k[15];
    #pragma unroll
    for (int d = 0; d < 8; d++) so[d] = k[2*d] + k[2*d + 1];

    // Load 12-value footprint: xs[j] = x[row, 4t + j - 4], zero outside [0,512)
    const float4* xr4 = reinterpret_cast<const float4*>(x + (size_t)row * W_IN);
    const float4 zero4 = make_float4(0.f, 0.f, 0.f, 0.f);
    float4 a = (t > 0)       ? __ldg(xr4 + (t - 1)) : zero4;
    float4 b =                 __ldg(xr4 + t);
    float4 c = (t < TPR - 1) ? __ldg(xr4 + (t + 1)) : zero4;

    float xs[12] = { a.x, a.y, a.z, a.w,
                     b.x, b.y, b.z, b.w,
                     c.x, c.y, c.z, c.w };

    float e0=0.f, e1=0.f, e2=0.f, e3=0.f;
    float o0=0.f, o1=0.f, o2=0.f, o3=0.f;
    #pragma unroll
    for (int d = 0; d < 9; d++) {
        const float w = se[d];
        e0 = fmaf(w, xs[d    ], e0);
        e1 = fmaf(w, xs[d + 1], e1);
        e2 = fmaf(w, xs[d + 2], e2);
        e3 = fmaf(w, xs[d + 3], e3);
    }
    #pragma unroll
    for (int d = 0; d < 8; d++) {
        const float w = so[d];
        o0 = fmaf(w, xs[d + 1], o0);
        o1 = fmaf(w, xs[d + 2], o1);
        o2 = fmaf(w, xs[d + 3], o2);
        o3 = fmaf(w, xs[d + 4], o3);
    }

    float4* s = reinterpret_cast<float4*>(&srow[half][8 * t]);
    s[0] = make_float4(e0, o0, e1, o1);
    s[1] = make_float4(e2, o2, e3, o3);

    __syncthreads();
    // Order generic-proxy SMEM writes before async-proxy (TMA) reads.
    asm volatile("fence.proxy.async.shared::cta;" ::: "memory");

    // 4 TMA bulk stores per block: each computed row is written twice
    // (output rows 2r and 2r+1 are contiguous 4KB each).
    if (threadIdx.x < 4) {
        const int h   = threadIdx.x >> 1;                 // which computed row
        const int dup = threadIdx.x & 1;                  // which duplicate
        const int rrow = blockIdx.x * 2 + h;
        const int n = rrow >> 9;
        const int r = rrow & 511;
        float* dst = out + ((size_t)n * 1024 + 2 * (size_t)r + dup) * W_OUT;
        uint32_t src = smem_u32(&srow[h][0]);
        asm volatile(
            "cp.async.bulk.global.shared::cta.bulk_group [%0], [%1], %2;"
            :: "l"(dst), "r"(src), "r"(W_OUT * 4) : "memory");
        asm volatile("cp.async.bulk.commit_group;" ::: "memory");
        // Full completion before CTA exit (SMEM lifetime + visibility).
        asm volatile("cp.async.bulk.wait_group 0;" ::: "memory");
    }
}

extern "C" void kernel_launch(void* const* d_in, const int* in_sizes, int n_in,
                              void* d_out, int out_size)
{
    const float* x   = (const float*)d_in[0];   // 32*512*512
    const float* ker = (const float*)d_in[1];   // 16 floats (4x4 row-major)
    float* out = (float*)d_out;                 // 32*1024*1024

    dim3 grid(32 * 512 / 2);   // 8192 blocks, 2 input rows each
    dim3 block(256);
    upfir_kernel<<<grid, block>>>(x, ker, out);
}